// round 7
// baseline (speedup 1.0000x reference)
#include <cuda_runtime.h>
#include <cstdint>

// Causal depthwise conv1d (K=4) + SiLU, fp32.
// y[b,t,c] = silu( bias[c] + sum_k w[c,k] * x[b, t-3+k, c] )
//
// R7: split-commit-group cp.async pipeline + occupancy push.
// Tile = 32 channel-quads x 64 time steps (67 smem rows, 34.3KB).
// Group 0 = rows 0..34, group 1 = rows 35..66. Compute of half 0 overlaps
// the in-flight loads of half 1. __launch_bounds__(256,5) -> 5 CTAs/SM.

constexpr int C4T = 32;              // channel-quads per block (128 channels)
constexpr int TS  = 64;              // time steps per block
constexpr int NR  = TS + 3;          // 67 smem rows (3-row causal halo)
constexpr int TPB = 256;             // 32 (c4) x 8 (time groups)
constexpr int HALF = TS / 2;         // 32
constexpr int RPH  = HALF / 8;       // 4 rows per thread per half

__device__ __forceinline__ float silu(float v) {
    return v / (1.0f + __expf(-v));
}

__device__ __forceinline__ void store_cs(float4* p, float4 v) {
    asm volatile("st.global.cs.v4.f32 [%0], {%1,%2,%3,%4};"
                 :: "l"(p), "f"(v.x), "f"(v.y), "f"(v.z), "f"(v.w) : "memory");
}

__device__ __forceinline__ void cp_async16(uint32_t smem_addr, const void* gptr) {
    asm volatile("cp.async.ca.shared.global [%0], [%1], 16;"
                 :: "r"(smem_addr), "l"(gptr) : "memory");
}

__global__ __launch_bounds__(TPB, 5)
void shortconv1d_kernel(const float* __restrict__ x,
                        const float* __restrict__ w,
                        const float* __restrict__ bias,
                        float* __restrict__ y,
                        int T, int C) {
    __shared__ float4 tile[NR * C4T];   // 67 * 32 * 16B = 34304 B

    const int Cd4    = C >> 2;
    const int tid    = threadIdx.x;
    const int cx     = tid & (C4T - 1);     // c4 lane within tile
    const int ty     = tid >> 5;            // time group 0..7
    const int c4base = blockIdx.x * C4T;
    const int c4g    = c4base + cx;
    const int b      = blockIdx.z;
    const int t0     = blockIdx.y * TS;

    const float4* __restrict__ x4 = reinterpret_cast<const float4*>(x);
    float4* __restrict__       y4 = reinterpret_cast<float4*>(y);

    const uint32_t smem_base = (uint32_t)__cvta_generic_to_shared(&tile[0]);
    const size_t   gRowBase  = (size_t)b * T * Cd4 + c4base;

    // ---- Group 0: smem rows 0..34  (= x rows t0-3 .. t0+31) ----
#pragma unroll
    for (int e = tid; e < 35 * C4T; e += TPB) {
        const int row = e >> 5;              // e / C4T
        const int cl  = e & (C4T - 1);
        const int t   = t0 - 3 + row;
        const uint32_t dst = smem_base + (uint32_t)e * 16u;
        if (t >= 0) {
            cp_async16(dst, &x4[gRowBase + (size_t)t * Cd4 + cl]);
        } else {
            asm volatile("st.shared.v4.b32 [%0], {%1,%1,%1,%1};"
                         :: "r"(dst), "r"(0) : "memory");
        }
    }
    asm volatile("cp.async.commit_group;" ::: "memory");

    // ---- Group 1: smem rows 35..66 (= x rows t0+32 .. t0+63) ----
#pragma unroll
    for (int e = tid; e < 32 * C4T; e += TPB) {
        const int row = 35 + (e >> 5);
        const int cl  = e & (C4T - 1);
        const int t   = t0 - 3 + row;        // always >= 32, in-bounds
        const uint32_t dst = smem_base + (uint32_t)(row * C4T + cl) * 16u;
        cp_async16(dst, &x4[gRowBase + (size_t)t * Cd4 + cl]);
    }
    asm volatile("cp.async.commit_group;" ::: "memory");

    // ---- Weights + bias while loads fly ----
    const int c = c4g << 2;
    const float4* __restrict__ w4 = reinterpret_cast<const float4*>(w);
    const float4 wl0 = w4[c + 0];
    const float4 wl1 = w4[c + 1];
    const float4 wl2 = w4[c + 2];
    const float4 wl3 = w4[c + 3];
    const float4 bi  = reinterpret_cast<const float4*>(bias)[c4g];

    float4* __restrict__ yp = &y4[((size_t)b * T + t0) * Cd4 + c4g];
    const size_t rs = (size_t)Cd4;

    // ================= Half 0: output rows [ty*RPH, ty*RPH+RPH) =============
    asm volatile("cp.async.wait_group 1;" ::: "memory");
    __syncthreads();
    {
        const int r0 = ty * RPH;             // 0..28
        float4 p0 = tile[(r0 + 0) * C4T + cx];
        float4 p1 = tile[(r0 + 1) * C4T + cx];
        float4 p2 = tile[(r0 + 2) * C4T + cx];
#pragma unroll
        for (int r = 0; r < RPH; ++r) {
            const float4 cv = tile[(r0 + 3 + r) * C4T + cx];
            float4 acc;
            acc.x = fmaf(wl0.x, p0.x, fmaf(wl0.y, p1.x, fmaf(wl0.z, p2.x, fmaf(wl0.w, cv.x, bi.x))));
            acc.y = fmaf(wl1.x, p0.y, fmaf(wl1.y, p1.y, fmaf(wl1.z, p2.y, fmaf(wl1.w, cv.y, bi.y))));
            acc.z = fmaf(wl2.x, p0.z, fmaf(wl2.y, p1.z, fmaf(wl2.z, p2.z, fmaf(wl2.w, cv.z, bi.z))));
            acc.w = fmaf(wl3.x, p0.w, fmaf(wl3.y, p1.w, fmaf(wl3.z, p2.w, fmaf(wl3.w, cv.w, bi.w))));
            float4 out;
            out.x = silu(acc.x); out.y = silu(acc.y);
            out.z = silu(acc.z); out.w = silu(acc.w);
            store_cs(yp + (size_t)(r0 + r) * rs, out);
            p0 = p1; p1 = p2; p2 = cv;
        }
    }

    // ================= Half 1: output rows 32 + [ty*RPH, ...) ===============
    asm volatile("cp.async.wait_group 0;" ::: "memory");
    __syncthreads();
    {
        const int r0 = HALF + ty * RPH;      // 32..60
        float4 p0 = tile[(r0 + 0) * C4T + cx];
        float4 p1 = tile[(r0 + 1) * C4T + cx];
        float4 p2 = tile[(r0 + 2) * C4T + cx];
#pragma unroll
        for (int r = 0; r < RPH; ++r) {
            const float4 cv = tile[(r0 + 3 + r) * C4T + cx];
            float4 acc;
            acc.x = fmaf(wl0.x, p0.x, fmaf(wl0.y, p1.x, fmaf(wl0.z, p2.x, fmaf(wl0.w, cv.x, bi.x))));
            acc.y = fmaf(wl1.x, p0.y, fmaf(wl1.y, p1.y, fmaf(wl1.z, p2.y, fmaf(wl1.w, cv.y, bi.y))));
            acc.z = fmaf(wl2.x, p0.z, fmaf(wl2.y, p1.z, fmaf(wl2.z, p2.z, fmaf(wl2.w, cv.z, bi.z))));
            acc.w = fmaf(wl3.x, p0.w, fmaf(wl3.y, p1.w, fmaf(wl3.z, p2.w, fmaf(wl3.w, cv.w, bi.w))));
            float4 out;
            out.x = silu(acc.x); out.y = silu(acc.y);
            out.z = silu(acc.z); out.w = silu(acc.w);
            store_cs(yp + (size_t)(r0 + r) * rs, out);
            p0 = p1; p1 = p2; p2 = cv;
        }
    }
}

extern "C" void kernel_launch(void* const* d_in, const int* in_sizes, int n_in,
                              void* d_out, int out_size) {
    const float* x    = (const float*)d_in[0];
    const float* w    = (const float*)d_in[1];
    const float* bias = (const float*)d_in[2];
    float* y          = (float*)d_out;

    const int C  = in_sizes[2];       // bias: (C,)
    const int BT = in_sizes[0] / C;   // B*T
    const int T  = 4096;
    const int B  = BT / T;

    dim3 block(TPB);
    dim3 grid((C / 4) / C4T, T / TS, B);
    shortconv1d_kernel<<<grid, block>>>(x, w, bias, y, T, C);
}

// round 8
// speedup vs baseline: 1.0474x; 1.0474x over previous
#include <cuda_runtime.h>
#include <cstdint>

// Causal depthwise conv1d (K=4) + SiLU, fp32.
// y[b,t,c] = silu( bias[c] + sum_k w[c,k] * x[b, t-3+k, c] )
//
// R8: direct-register, no smem. Each thread: 7 front-batched LDG.128 over
// x[t0-3 .. t0+3] for one channel-quad -> 4 outputs via sliding window.
// Minimizes L1tex wavefronts (no STS/LDS round trip) and instruction count;
// relies on L2 to dedupe the 1.75x read amplification across adjacent
// t-blocks. launch_bounds(256,4) pins regs at 64 -> 32 warps/SM.

constexpr int TT  = 4;               // outputs per thread
constexpr int NW  = TT + 3;          // 7 window loads
constexpr int TPB = 256;

__device__ __forceinline__ float silu(float v) {
    return v / (1.0f + __expf(-v));
}

__device__ __forceinline__ void store_cs(float4* p, float4 v) {
    asm volatile("st.global.cs.v4.f32 [%0], {%1,%2,%3,%4};"
                 :: "l"(p), "f"(v.x), "f"(v.y), "f"(v.z), "f"(v.w) : "memory");
}

__global__ __launch_bounds__(TPB, 4)
void shortconv1d_kernel(const float* __restrict__ x,
                        const float* __restrict__ w,
                        const float* __restrict__ bias,
                        float* __restrict__ y,
                        int T, int C) {
    const int Cd4 = C >> 2;
    const int c4  = blockIdx.x * TPB + threadIdx.x;
    const int c   = c4 << 2;
    const int b   = blockIdx.z;
    const int t0  = blockIdx.y * TT;

    const float4* __restrict__ x4 = reinterpret_cast<const float4*>(x);
    float4* __restrict__       y4 = reinterpret_cast<float4*>(y);

    const size_t rs   = (size_t)Cd4;
    const size_t base = ((size_t)b * T + t0) * rs + c4;   // element at (b,t0,c4)

    // ---- Front-batched window: x[t0-3 .. t0+3] (7 LDG.128 burst) ----
    float4 v[NW];
    if (t0 >= 3) {
#pragma unroll
        for (int i = 0; i < NW; ++i)
            v[i] = x4[base + (size_t)(i - 3) * rs];
    } else {
        const float4 z = make_float4(0.f, 0.f, 0.f, 0.f);
#pragma unroll
        for (int i = 0; i < NW; ++i) {
            const int t = t0 + i - 3;
            v[i] = (t >= 0) ? x4[base + (size_t)(i - 3) * rs] : z;
        }
    }

    // ---- Weights (contiguous float4 per channel) + bias ----
    const float4* __restrict__ w4 = reinterpret_cast<const float4*>(w);
    const float4 wl0 = w4[c + 0];
    const float4 wl1 = w4[c + 1];
    const float4 wl2 = w4[c + 2];
    const float4 wl3 = w4[c + 3];
    const float4 bi  = reinterpret_cast<const float4*>(bias)[c4];

    // ---- 4 outputs via sliding window ----
#pragma unroll
    for (int i = 0; i < TT; ++i) {
        const float4 a0 = v[i], a1 = v[i + 1], a2 = v[i + 2], a3 = v[i + 3];
        float4 acc;
        acc.x = fmaf(wl0.x, a0.x, fmaf(wl0.y, a1.x, fmaf(wl0.z, a2.x, fmaf(wl0.w, a3.x, bi.x))));
        acc.y = fmaf(wl1.x, a0.y, fmaf(wl1.y, a1.y, fmaf(wl1.z, a2.y, fmaf(wl1.w, a3.y, bi.y))));
        acc.z = fmaf(wl2.x, a0.z, fmaf(wl2.y, a1.z, fmaf(wl2.z, a2.z, fmaf(wl2.w, a3.z, bi.z))));
        acc.w = fmaf(wl3.x, a0.w, fmaf(wl3.y, a1.w, fmaf(wl3.z, a2.w, fmaf(wl3.w, a3.w, bi.w))));

        float4 out;
        out.x = silu(acc.x);
        out.y = silu(acc.y);
        out.z = silu(acc.z);
        out.w = silu(acc.w);

        store_cs(&y4[base + (size_t)i * rs], out);
    }
}

extern "C" void kernel_launch(void* const* d_in, const int* in_sizes, int n_in,
                              void* d_out, int out_size) {
    const float* x    = (const float*)d_in[0];
    const float* w    = (const float*)d_in[1];
    const float* bias = (const float*)d_in[2];
    float* y          = (float*)d_out;

    const int C  = in_sizes[2];       // bias: (C,)
    const int BT = in_sizes[0] / C;   // B*T
    const int T  = 4096;
    const int B  = BT / T;

    dim3 block(TPB);
    dim3 grid((C / 4 + TPB - 1) / TPB, T / TT, B);
    shortconv1d_kernel<<<grid, block>>>(x, w, bias, y, T, C);
}

// round 9
// speedup vs baseline: 1.0818x; 1.0328x over previous
#include <cuda_runtime.h>
#include <cstdint>

// Causal depthwise conv1d (K=4) + SiLU, fp32.
// y[b,t,c] = silu( bias[c] + sum_k w[c,k] * x[b, t-3+k, c] )
//
// R9: persistent single-wave kernel. Grid = 592 CTAs (4/SM x 148, one wave).
// Each thread owns one float4 channel-group + its weights for the whole
// kernel and grid-strides over all (b, t-tile) tiles, running the R8 body
// (7 front-batched LDG.128 -> 4 outputs). Eliminates ~13 wave transitions
// and per-wave launch/drain bubbles; keeps loads in flight continuously.

constexpr int TT   = 4;              // outputs per tile per thread
constexpr int NW   = TT + 3;         // 7 window loads
constexpr int TPB  = 256;
constexpr int NBLK_Y = 296;          // 2 * 296 = 592 CTAs = 4/SM * 148

__device__ __forceinline__ float silu(float v) {
    return v / (1.0f + __expf(-v));
}

__device__ __forceinline__ void store_cs(float4* p, float4 v) {
    asm volatile("st.global.cs.v4.f32 [%0], {%1,%2,%3,%4};"
                 :: "l"(p), "f"(v.x), "f"(v.y), "f"(v.z), "f"(v.w) : "memory");
}

__global__ __launch_bounds__(TPB, 4)
void shortconv1d_kernel(const float* __restrict__ x,
                        const float* __restrict__ w,
                        const float* __restrict__ bias,
                        float* __restrict__ y,
                        int T, int C, int B) {
    const int Cd4 = C >> 2;
    const int c4  = blockIdx.x * TPB + threadIdx.x;
    const int c   = c4 << 2;

    // ---- Per-thread invariants: weights + bias, loaded once ----
    const float4* __restrict__ w4 = reinterpret_cast<const float4*>(w);
    const float4 wl0 = w4[c + 0];
    const float4 wl1 = w4[c + 1];
    const float4 wl2 = w4[c + 2];
    const float4 wl3 = w4[c + 3];
    const float4 bi  = reinterpret_cast<const float4*>(bias)[c4];

    const float4* __restrict__ x4 = reinterpret_cast<const float4*>(x);
    float4* __restrict__       y4 = reinterpret_cast<float4*>(y);
    const size_t rs = (size_t)Cd4;

    const int tilesPerB = T / TT;          // 1024
    const int nTiles    = B * tilesPerB;   // 4096

    // ---- Persistent grid-stride loop over (b, t0) tiles ----
    for (int tile = blockIdx.y; tile < nTiles; tile += NBLK_Y) {
        const int b  = tile / tilesPerB;
        const int t0 = (tile - b * tilesPerB) * TT;

        const size_t base = ((size_t)b * T + t0) * rs + c4;

        // 7-load burst: x[t0-3 .. t0+3] for this channel-quad.
        float4 v[NW];
        if (t0 >= 3) {
#pragma unroll
            for (int i = 0; i < NW; ++i)
                v[i] = x4[base + (size_t)(i - 3) * rs];
        } else {
            const float4 z = make_float4(0.f, 0.f, 0.f, 0.f);
#pragma unroll
            for (int i = 0; i < NW; ++i) {
                const int t = t0 + i - 3;   // per-batch time (no cross-batch reads)
                v[i] = (t >= 0) ? x4[base + (size_t)(i - 3) * rs] : z;
            }
        }

#pragma unroll
        for (int i = 0; i < TT; ++i) {
            const float4 a0 = v[i], a1 = v[i + 1], a2 = v[i + 2], a3 = v[i + 3];
            float4 acc;
            acc.x = fmaf(wl0.x, a0.x, fmaf(wl0.y, a1.x, fmaf(wl0.z, a2.x, fmaf(wl0.w, a3.x, bi.x))));
            acc.y = fmaf(wl1.x, a0.y, fmaf(wl1.y, a1.y, fmaf(wl1.z, a2.y, fmaf(wl1.w, a3.y, bi.y))));
            acc.z = fmaf(wl2.x, a0.z, fmaf(wl2.y, a1.z, fmaf(wl2.z, a2.z, fmaf(wl2.w, a3.z, bi.z))));
            acc.w = fmaf(wl3.x, a0.w, fmaf(wl3.y, a1.w, fmaf(wl3.z, a2.w, fmaf(wl3.w, a3.w, bi.w))));

            float4 out;
            out.x = silu(acc.x);
            out.y = silu(acc.y);
            out.z = silu(acc.z);
            out.w = silu(acc.w);

            store_cs(&y4[base + (size_t)i * rs], out);
        }
    }
}

extern "C" void kernel_launch(void* const* d_in, const int* in_sizes, int n_in,
                              void* d_out, int out_size) {
    const float* x    = (const float*)d_in[0];
    const float* w    = (const float*)d_in[1];
    const float* bias = (const float*)d_in[2];
    float* y          = (float*)d_out;

    const int C  = in_sizes[2];       // bias: (C,)
    const int BT = in_sizes[0] / C;   // B*T
    const int T  = 4096;
    const int B  = BT / T;

    dim3 block(TPB);
    dim3 grid((C / 4 + TPB - 1) / TPB, NBLK_Y, 1);   // (2, 296) = 592 CTAs
    shortconv1d_kernel<<<grid, block>>>(x, w, bias, y, T, C, B);
}

// round 11
// speedup vs baseline: 1.1421x; 1.0557x over previous
#include <cuda_runtime.h>
#include <cstdint>

// Causal depthwise conv1d (K=4) + SiLU, fp32.
// y[b,t,c] = silu( bias[c] + sum_k w[c,k] * x[b, t-3+k, c] )
//
// R11 (= R10 resubmit after infra failure): float2 channel granularity
// (half the per-thread registers of the float4 variants -> 6 CTAs/SM,
// 48 warps = 75% occupancy) + fast SiLU (MUFU rcp instead of the
// full-precision divide sequence). TT=4 window.

constexpr int TT  = 4;               // outputs per thread
constexpr int NW  = TT + 3;          // 7 window loads
constexpr int TPB = 256;

__device__ __forceinline__ float fast_silu(float v) {
    // v * rcp(1 + exp(-v)):  EX2-based expf + MUFU.RCP (rel err ~1e-7)
    float e = __expf(-v);
    float r;
    asm("rcp.approx.f32 %0, %1;" : "=f"(r) : "f"(1.0f + e));
    return v * r;
}

__device__ __forceinline__ void store_cs2(float2* p, float2 v) {
    asm volatile("st.global.cs.v2.f32 [%0], {%1,%2};"
                 :: "l"(p), "f"(v.x), "f"(v.y) : "memory");
}

__global__ __launch_bounds__(TPB, 6)
void shortconv1d_kernel(const float* __restrict__ x,
                        const float* __restrict__ w,
                        const float* __restrict__ bias,
                        float* __restrict__ y,
                        int T, int C) {
    const int Cd2 = C >> 1;
    const int c2  = blockIdx.x * TPB + threadIdx.x;  // float2 channel-group
    const int c   = c2 << 1;
    const int b   = blockIdx.z;
    const int t0  = blockIdx.y * TT;

    const float2* __restrict__ x2 = reinterpret_cast<const float2*>(x);
    float2* __restrict__       y2 = reinterpret_cast<float2*>(y);

    const size_t rs   = (size_t)Cd2;
    const size_t base = ((size_t)b * T + t0) * rs + c2;

    // ---- Front-batched window: x[t0-3 .. t0+3] (7 LDG.64 burst) ----
    float2 v[NW];
    if (t0 >= 3) {
#pragma unroll
        for (int i = 0; i < NW; ++i)
            v[i] = x2[base + (size_t)(i - 3) * rs];
    } else {
        const float2 z = make_float2(0.f, 0.f);
#pragma unroll
        for (int i = 0; i < NW; ++i) {
            const int t = t0 + i - 3;
            v[i] = (t >= 0) ? x2[base + (size_t)(i - 3) * rs] : z;
        }
    }

    // ---- Weights: 2 channels -> 2 contiguous float4 rows; bias float2 ----
    const float4* __restrict__ w4 = reinterpret_cast<const float4*>(w);
    const float4 wa = w4[c + 0];
    const float4 wb = w4[c + 1];
    const float2 bi = reinterpret_cast<const float2*>(bias)[c2];

    // ---- 4 outputs via sliding window ----
#pragma unroll
    for (int i = 0; i < TT; ++i) {
        const float2 a0 = v[i], a1 = v[i + 1], a2 = v[i + 2], a3 = v[i + 3];
        float2 acc;
        acc.x = fmaf(wa.x, a0.x, fmaf(wa.y, a1.x, fmaf(wa.z, a2.x, fmaf(wa.w, a3.x, bi.x))));
        acc.y = fmaf(wb.x, a0.y, fmaf(wb.y, a1.y, fmaf(wb.z, a2.y, fmaf(wb.w, a3.y, bi.y))));

        float2 out;
        out.x = fast_silu(acc.x);
        out.y = fast_silu(acc.y);

        store_cs2(&y2[base + (size_t)i * rs], out);
    }
}

extern "C" void kernel_launch(void* const* d_in, const int* in_sizes, int n_in,
                              void* d_out, int out_size) {
    const float* x    = (const float*)d_in[0];
    const float* w    = (const float*)d_in[1];
    const float* bias = (const float*)d_in[2];
    float* y          = (float*)d_out;

    const int C  = in_sizes[2];       // bias: (C,)
    const int BT = in_sizes[0] / C;   // B*T
    const int T  = 4096;
    const int B  = BT / T;

    dim3 block(TPB);
    dim3 grid((C / 2 + TPB - 1) / TPB, T / TT, B);
    shortconv1d_kernel<<<grid, block>>>(x, w, bias, y, T, C);
}